// round 11
// baseline (speedup 1.0000x reference)
#include <cuda_runtime.h>
#include <math.h>

#define BB   128
#define SS   512
#define CC   256
#define DOO  4
#define GG   10
#define NCTA 128
#define TPB  512

#define OUT_PI   (BB*SS*DOO)
#define OUT_SG   (OUT_PI + BB*SS*GG)
#define OUT_MU   (OUT_SG + BB*SS*GG*DOO)
#define OUT_MASK (OUT_MU + BB*SS*GG*DOO)

__device__ float g_pn[BB*SS*DOO];
__device__ float g_gi0[(size_t)SS*768*BB];
__device__ float g_h0[2][256*BB];
__device__ float g_h1[2][256*BB];
__device__ float g_H[(size_t)SS*256*BB];
__device__ unsigned int g_flag[4][64];     // [stream = pr*2+half][ug]

__device__ __forceinline__ float sigmoidf_(float x){ return 1.f/(1.f + expf(-x)); }
__device__ __forceinline__ void ffma2(unsigned long long &acc,
                                      unsigned long long a, unsigned long long b){
    asm("fma.rn.f32x2 %0, %1, %2, %0;" : "+l"(acc) : "l"(a), "l"(b));
}
__device__ __forceinline__ float2 u2f2(unsigned long long v){
    float2 f; asm("mov.b64 {%0,%1}, %2;" : "=f"(f.x), "=f"(f.y) : "l"(v)); return f;
}

__global__ void init_kernel(){
    int i = blockIdx.x*256 + threadIdx.x;
    if (i < 256) ((unsigned int*)g_flag)[i] = 0u;
    g_h0[0][i] = 0.f; g_h0[1][i] = 0.f;
    g_h1[0][i] = 0.f; g_h1[1][i] = 0.f;
}

__global__ void prenet_kernel(const float* __restrict__ tgt,
                              const float* __restrict__ W_pre,
                              const float* __restrict__ b_pre){
    int idx = blockIdx.x*256 + threadIdx.x;
    if (idx >= BB*SS*DOO) return;
    int d = idx & 3, s = (idx >> 2) & (SS-1), b = idx >> 11;
    float v = b_pre[d];
    if (s > 0){
        const float* pv = tgt + ((size_t)(b*SS + s - 1))*DOO;
        #pragma unroll
        for (int e = 0; e < 4; e++) v += pv[e]*W_pre[d*DOO + e];
    }
    g_pn[idx] = v;
}

__global__ __launch_bounds__(256) void gi0_gemm(const float* __restrict__ enc,
                                                const float* __restrict__ Wih0,
                                                const float* __restrict__ bih0){
    __shared__ float As[32][68];
    __shared__ float Wd[32][132];
    const int s  = blockIdx.z, c0 = blockIdx.y*64, b0 = blockIdx.x*64;
    const int t  = threadIdx.x, bg = t & 15, cg = t >> 4;
    unsigned long long acc[4][2];
    #pragma unroll
    for (int i = 0; i < 4; i++){ acc[i][0] = 0ULL; acc[i][1] = 0ULL; }

    for (int kk = 0; kk < 260; kk += 32){
        for (int i = t; i < 512; i += 256){
            int b = i >> 3, kq = i & 7, kg = kk + kq*4;
            float4 v = make_float4(0.f,0.f,0.f,0.f);
            if (kg < 256)       v = *(const float4*)&enc[(((size_t)(b0+b))*SS + s)*CC + kg];
            else if (kg == 256) v = *(const float4*)&g_pn[(((size_t)(b0+b))*SS + s)*DOO];
            int k = kq*4;
            As[k][b] = v.x; As[k+1][b] = v.y; As[k+2][b] = v.z; As[k+3][b] = v.w;
        }
        for (int i = t; i < 512; i += 256){
            int c = i >> 3, kq = i & 7, kg = kk + kq*4;
            float4 v = make_float4(0.f,0.f,0.f,0.f);
            if (kg <= 256) v = *(const float4*)&Wih0[(size_t)(c0+c)*260 + kg];
            int k = kq*4;
            Wd[k][2*c] = v.x;   Wd[k][2*c+1] = v.x;
            Wd[k+1][2*c] = v.y; Wd[k+1][2*c+1] = v.y;
            Wd[k+2][2*c] = v.z; Wd[k+2][2*c+1] = v.z;
            Wd[k+3][2*c] = v.w; Wd[k+3][2*c+1] = v.w;
        }
        __syncthreads();
        #pragma unroll 8
        for (int k = 0; k < 32; k++){
            ulonglong2 a   = *(const ulonglong2*)&As[k][bg*4];
            ulonglong2 w01 = *(const ulonglong2*)&Wd[k][cg*8];
            ulonglong2 w23 = *(const ulonglong2*)&Wd[k][cg*8+4];
            ffma2(acc[0][0], a.x, w01.x); ffma2(acc[0][1], a.y, w01.x);
            ffma2(acc[1][0], a.x, w01.y); ffma2(acc[1][1], a.y, w01.y);
            ffma2(acc[2][0], a.x, w23.x); ffma2(acc[2][1], a.y, w23.x);
            ffma2(acc[3][0], a.x, w23.y); ffma2(acc[3][1], a.y, w23.y);
        }
        __syncthreads();
    }
    #pragma unroll
    for (int ci = 0; ci < 4; ci++){
        int c = c0 + cg*4 + ci;
        float bias = bih0[c];
        float2 p0 = u2f2(acc[ci][0]), p1 = u2f2(acc[ci][1]);
        *(float4*)&g_gi0[((size_t)s*768 + c)*BB + b0 + bg*4] =
            make_float4(p0.x+bias, p0.y+bias, p1.x+bias, p1.y+bias);
    }
}

// persistent GRU recurrence: two INDEPENDENT half-CTAs (8 warps, 32 batches each).
// No intra-CTA sync between halves — half X's barrier/poll bubble is hidden by
// half Y's compute. Per half: 6 A-warps (rows 0-23: gh0+gi1, hs0) + 2 B-warps
// (rows gh1, hs1), each warp one k-half. B-warps on different SMSPs per half.
__global__ void __launch_bounds__(TPB, 1) rec_kernel(
    const float* __restrict__ Whh0, const float* __restrict__ bhh0,
    const float* __restrict__ Wih1, const float* __restrict__ bih1,
    const float* __restrict__ Whh1, const float* __restrict__ bhh1)
{
    extern __shared__ float sm[];
    float* wqA = sm;                 // 12288 : A rows 0-23 [r3][k][16 dup-pairs]
    float* wBq = wqA + 12288;        // 8192  : B rows [k][32: 4sg x 3 dup-pairs+pad]
    float* hs0 = wBq + 8192;         // 16384 : per-half 8192 = 256u x 32b
    float* hs1 = hs0 + 16384;        // 16384
    float* pA  = hs1 + 16384;        // 3072  : per-half 2kh x 24r x 32b
    float* pB  = pA + 3072;          // 1536  : per-half 2kh x 12r x 32b

    const int t = threadIdx.x, w = t >> 5, l = t & 31;
    const int half = t >> 8, hw = w & 7, ht = t & 255;
    const int ug = blockIdx.x >> 1, pr = blockIdx.x & 1;
    const int u0 = ug*4;
    const int strm = pr*2 + half;
    const int b0s = pr*64 + half*32;
    float* hs0h = hs0 + half*8192;
    float* hs1h = hs1 + half*8192;
    float* pAh  = pA + half*1536;
    float* pBh  = pB + half*768;
    const unsigned int* fl = g_flag[strm];

    for (int i = t; i < 24*256; i += TPB){
        int row = i >> 8, k = i & 255;
        int g3 = row/12, rr = row - g3*12;
        int ui2 = rr/3, g = rr - ui2*3;
        const float* W = (g3 == 0) ? Whh0 : Wih1;
        float v = W[(size_t)(g*256 + u0 + ui2)*256 + k];
        int off = (row >> 3)*4096 + k*16 + (row & 7)*2;
        wqA[off] = v; wqA[off+1] = v;
    }
    for (int i = t; i < 12*256; i += TPB){
        int row = i >> 8, k = i & 255;
        int ui2 = row/3, g = row - ui2*3;
        float v = Whh1[(size_t)(g*256 + u0 + ui2)*256 + k];
        int off = k*32 + ui2*8 + (row - ui2*3)*2;
        wBq[off] = v; wBq[off+1] = v;
    }

    // warp roles (B-warps on distinct SMSPs per half)
    bool isB; int kh, r3 = 0;
    if (half == 0){
        isB = (hw >= 6);
        if (isB) kh = hw - 6; else { r3 = hw >> 1; kh = hw & 1; }
    } else {
        isB = (hw == 4 || hw == 5);
        if (isB) kh = hw - 4;
        else { int a = (hw < 4) ? hw : hw - 2; r3 = a >> 1; kh = a & 1; }
    }
    const int sg = l >> 3, lb = l & 7;

    // update-thread constants
    const int uui = (ht & 127) >> 5, ubl = ht & 31, uu = u0 + uui;
    float b0r=0,b0z=0,b0n=0,b1ir=0,b1iz=0,b1in=0,b1hr=0,b1hz=0,b1hn=0;
    if (ht < 128){
        b0r=bhh0[uu]; b0z=bhh0[256+uu]; b0n=bhh0[512+uu];
    } else {
        b1ir=bih1[uu]; b1iz=bih1[256+uu]; b1in=bih1[512+uu];
        b1hr=bhh1[uu]; b1hz=bhh1[256+uu]; b1hn=bhh1[512+uu];
    }
    __syncthreads();   // weights ready (once, before loop)

    for (int ph = 0; ph < 513; ph++){
        const float* src0 = g_h0[(ph+1) & 1];
        const float* src1 = g_h1[ph & 1];
        float* dst0 = g_h0[ph & 1];
        float* dst1 = g_h1[(ph+1) & 1];

        // poll all 64 producer flags of this stream (warp 0 of half)
        if (hw == 0){
            bool ok;
            do {
                unsigned int m = 0xffffffffu;
                if (l < 16){
                    unsigned int a,b,c,d;
                    asm volatile("ld.volatile.global.v4.u32 {%0,%1,%2,%3}, [%4];"
                                 : "=r"(a), "=r"(b), "=r"(c), "=r"(d) : "l"(fl + l*4));
                    m = min(min(a,b), min(c,d));
                }
                ok = __all_sync(0xffffffffu, m >= (unsigned int)ph);
            } while (!ok);
            __threadfence();
        }
        asm volatile("bar.sync %0, 256;" :: "r"(1 + half) : "memory");

        // prefetch update inputs
        float gir=0.f, giz=0.f, gin=0.f, hold=0.f;
        if (ht < 128){
            hold = __ldcg(&src0[uu*BB + b0s + ubl]);
            if (ph < 512){
                const float* gb = g_gi0 + (size_t)ph*768*BB;
                gir = __ldcg(&gb[(size_t)uu*BB       + b0s + ubl]);
                giz = __ldcg(&gb[(size_t)(256+uu)*BB + b0s + ubl]);
                gin = __ldcg(&gb[(size_t)(512+uu)*BB + b0s + ubl]);
            }
        } else {
            hold = __ldcg(&src1[uu*BB + b0s + ubl]);
        }

        // stage this half's 32-batch h tiles
        for (int j = ht; j < 2048; j += 256)
            ((float4*)hs0h)[j] = __ldcg((const float4*)&src0[(j>>3)*BB + b0s + (j&7)*4]);
        for (int j = ht; j < 2048; j += 256)
            ((float4*)hs1h)[j] = __ldcg((const float4*)&src1[(j>>3)*BB + b0s + (j&7)*4]);
        asm volatile("bar.sync %0, 256;" :: "r"(1 + half) : "memory");

        if (!isB){
            const float* hp = hs0h + kh*4096 + lb*4;
            const float* wp = wqA + r3*4096 + kh*2048 + sg*4;
            unsigned long long a00=0,a01=0,a10=0,a11=0;
            #pragma unroll 16
            for (int k = 0; k < 128; k++){
                ulonglong2 hq = *(const ulonglong2*)(hp + k*32);
                ulonglong2 wv = *(const ulonglong2*)(wp + k*16);
                ffma2(a00, hq.x, wv.x); ffma2(a01, hq.y, wv.x);
                ffma2(a10, hq.x, wv.y); ffma2(a11, hq.y, wv.y);
            }
            const int row0 = r3*8 + 2*sg;
            float2 p0, p1;
            p0 = u2f2(a00); p1 = u2f2(a01);
            *(float4*)&pAh[(kh*24 + row0)*32 + lb*4]   = make_float4(p0.x,p0.y,p1.x,p1.y);
            p0 = u2f2(a10); p1 = u2f2(a11);
            *(float4*)&pAh[(kh*24 + row0+1)*32 + lb*4] = make_float4(p0.x,p0.y,p1.x,p1.y);
        } else {
            const float* hp = hs1h + kh*4096 + lb*4;
            const float* wp = wBq + kh*4096 + sg*8;
            unsigned long long c00=0,c01=0,c10=0,c11=0,c20=0,c21=0;
            #pragma unroll 16
            for (int k = 0; k < 128; k++){
                ulonglong2 hq = *(const ulonglong2*)(hp + k*32);
                ulonglong2 wv = *(const ulonglong2*)(wp + k*32);
                unsigned long long w2 = *(const unsigned long long*)(wp + k*32 + 4);
                ffma2(c00, hq.x, wv.x); ffma2(c01, hq.y, wv.x);
                ffma2(c10, hq.x, wv.y); ffma2(c11, hq.y, wv.y);
                ffma2(c20, hq.x, w2);   ffma2(c21, hq.y, w2);
            }
            const int rb = kh*12 + sg*3;
            float2 p0, p1;
            p0 = u2f2(c00); p1 = u2f2(c01);
            *(float4*)&pBh[(rb+0)*32 + lb*4] = make_float4(p0.x,p0.y,p1.x,p1.y);
            p0 = u2f2(c10); p1 = u2f2(c11);
            *(float4*)&pBh[(rb+1)*32 + lb*4] = make_float4(p0.x,p0.y,p1.x,p1.y);
            p0 = u2f2(c20); p1 = u2f2(c21);
            *(float4*)&pBh[(rb+2)*32 + lb*4] = make_float4(p0.x,p0.y,p1.x,p1.y);
        }
        asm volatile("bar.sync %0, 256;" :: "r"(1 + half) : "memory");

        if (ht < 128){
            if (ph < 512){
                int r0 = uui*3;
                float s0 = pAh[r0*32+ubl]     + pAh[(24+r0)*32+ubl];
                float s1 = pAh[(r0+1)*32+ubl] + pAh[(24+r0+1)*32+ubl];
                float s2 = pAh[(r0+2)*32+ubl] + pAh[(24+r0+2)*32+ubl];
                float r = sigmoidf_(gir + s0 + b0r);
                float z = sigmoidf_(giz + s1 + b0z);
                float n = tanhf(gin + r*(s2 + b0n));
                dst0[uu*BB + b0s + ubl] = 0.1f*hold + 0.9f*((1.f - z)*n + z*hold);
            }
        } else {
            if (ph >= 1){
                int r0 = uui*3, q0 = 12 + r0;
                float i0 = pAh[q0*32+ubl]     + pAh[(24+q0)*32+ubl]   + b1ir;
                float i1 = pAh[(q0+1)*32+ubl] + pAh[(24+q0+1)*32+ubl] + b1iz;
                float i2 = pAh[(q0+2)*32+ubl] + pAh[(24+q0+2)*32+ubl] + b1in;
                float hg0 = pBh[r0*32+ubl]     + pBh[(12+r0)*32+ubl]   + b1hr;
                float hg1 = pBh[(r0+1)*32+ubl] + pBh[(12+r0+1)*32+ubl] + b1hz;
                float hg2 = pBh[(r0+2)*32+ubl] + pBh[(12+r0+2)*32+ubl] + b1hn;
                float r = sigmoidf_(i0 + hg0);
                float z = sigmoidf_(i1 + hg1);
                float n = tanhf(i2 + r*hg2);
                float hout = 0.1f*hold + 0.9f*((1.f - z)*n + z*hold);
                dst1[uu*BB + b0s + ubl] = hout;
                g_H[((size_t)(ph-1)*256 + uu)*BB + b0s + ubl] = hout;
            }
        }
        asm volatile("bar.sync %0, 256;" :: "r"(1 + half) : "memory");
        if (ht == 0){
            __threadfence();
            *(volatile unsigned int*)&g_flag[strm][ug] = (unsigned int)(ph+1);
        }
    }
}

__global__ __launch_bounds__(256) void out_gemm(const float* __restrict__ enc,
    const float* __restrict__ Wpi, const float* __restrict__ bpi,
    const float* __restrict__ Wsg, const float* __restrict__ bsg,
    const float* __restrict__ Wmu, const float* __restrict__ bmu,
    float* __restrict__ out)
{
    __shared__ float As[32][68];
    __shared__ float Wd[32][196];
    __shared__ float Rs[64][96];
    const int s  = blockIdx.y, b0 = blockIdx.x*64;
    const int t  = threadIdx.x, bg = t & 15, cg = t >> 4;
    unsigned long long acc[6][2];
    #pragma unroll
    for (int i = 0; i < 6; i++){ acc[i][0] = 0ULL; acc[i][1] = 0ULL; }

    for (int kk = 0; kk < 512; kk += 32){
        if (kk < 256){
            for (int i = t; i < 2048; i += 256){
                int k = i >> 6, b = i & 63;
                As[k][b] = g_H[((size_t)s*256 + kk + k)*BB + b0 + b];
            }
        } else {
            for (int i = t; i < 512; i += 256){
                int b = i >> 3, kq = i & 7, kg = kk - 256 + kq*4;
                float4 v = *(const float4*)&enc[(((size_t)(b0+b))*SS + s)*CC + kg];
                int k = kq*4;
                As[k][b] = v.x; As[k+1][b] = v.y; As[k+2][b] = v.z; As[k+3][b] = v.w;
            }
        }
        for (int i = t; i < 768; i += 256){
            int c = i >> 3, kq = i & 7, kg = kk + kq*4;
            float4 v = make_float4(0.f,0.f,0.f,0.f);
            if      (c < 10) v = *(const float4*)&Wpi[(size_t)c*512 + kg];
            else if (c < 50) v = *(const float4*)&Wsg[(size_t)(c-10)*512 + kg];
            else if (c < 90) v = *(const float4*)&Wmu[(size_t)(c-50)*512 + kg];
            int k = kq*4;
            Wd[k][2*c] = v.x;   Wd[k][2*c+1] = v.x;
            Wd[k+1][2*c] = v.y; Wd[k+1][2*c+1] = v.y;
            Wd[k+2][2*c] = v.z; Wd[k+2][2*c+1] = v.z;
            Wd[k+3][2*c] = v.w; Wd[k+3][2*c+1] = v.w;
        }
        __syncthreads();
        #pragma unroll 4
        for (int k = 0; k < 32; k++){
            ulonglong2 a   = *(const ulonglong2*)&As[k][bg*4];
            ulonglong2 w01 = *(const ulonglong2*)&Wd[k][cg*12];
            ulonglong2 w23 = *(const ulonglong2*)&Wd[k][cg*12+4];
            ulonglong2 w45 = *(const ulonglong2*)&Wd[k][cg*12+8];
            ffma2(acc[0][0], a.x, w01.x); ffma2(acc[0][1], a.y, w01.x);
            ffma2(acc[1][0], a.x, w01.y); ffma2(acc[1][1], a.y, w01.y);
            ffma2(acc[2][0], a.x, w23.x); ffma2(acc[2][1], a.y, w23.x);
            ffma2(acc[3][0], a.x, w23.y); ffma2(acc[3][1], a.y, w23.y);
            ffma2(acc[4][0], a.x, w45.x); ffma2(acc[4][1], a.y, w45.x);
            ffma2(acc[5][0], a.x, w45.y); ffma2(acc[5][1], a.y, w45.y);
        }
        __syncthreads();
    }
    #pragma unroll
    for (int ci = 0; ci < 6; ci++){
        int c = cg*6 + ci;
        float bias = (c < 10) ? bpi[c] : (c < 50) ? bsg[c-10] : (c < 90) ? bmu[c-50] : 0.f;
        float2 p0 = u2f2(acc[ci][0]), p1 = u2f2(acc[ci][1]);
        Rs[bg*4+0][c] = p0.x + bias;
        Rs[bg*4+1][c] = p0.y + bias;
        Rs[bg*4+2][c] = p1.x + bias;
        Rs[bg*4+3][c] = p1.y + bias;
    }
    __syncthreads();

    if (t < 64){
        int b = b0 + t;
        float lv[10]; float m = -1e30f;
        #pragma unroll
        for (int g = 0; g < 10; g++){ lv[g] = Rs[t][g]; m = fmaxf(m, lv[g]); }
        float sum = 0.f;
        #pragma unroll
        for (int g = 0; g < 10; g++){ lv[g] = expf(lv[g]-m); sum += lv[g]; }
        float inv = 1.f/sum;
        size_t base = (size_t)OUT_PI + ((size_t)b*SS + s)*10;
        #pragma unroll
        for (int g = 0; g < 10; g++) out[base + g] = lv[g]*inv;
    }
    for (int i = t; i < 64*40; i += 256){
        int row = i/40, j = i - row*40, b = b0 + row;
        float x  = Rs[row][10+j];
        float xm = Rs[row][50+j];
        size_t base = ((size_t)b*SS + s)*40 + j;
        out[(size_t)OUT_SG + base] = (x > 0.f) ? (x + 1.f) : expf(x);
        out[(size_t)OUT_MU + base] = xm;
    }
}

__global__ void tail_kernel(const float* __restrict__ tgt,
                            const int* __restrict__ dur,
                            float* __restrict__ out){
    if (blockIdx.x < 1024){
        int idx = blockIdx.x*256 + threadIdx.x;
        out[idx] = tgt[idx];
    } else {
        int b = blockIdx.x - 1024;
        __shared__ int cnt;
        if (threadIdx.x == 0) cnt = 0;
        __syncthreads();
        int local = 0;
        for (int s = threadIdx.x; s < SS; s += 256) local += (dur[b*SS + s] > 0) ? 1 : 0;
        #pragma unroll
        for (int o = 16; o; o >>= 1) local += __shfl_down_sync(0xffffffffu, local, o);
        if ((threadIdx.x & 31) == 0) atomicAdd(&cnt, local);
        __syncthreads();
        int c = cnt;
        for (int s = threadIdx.x; s < SS; s += 256)
            out[OUT_MASK + b*SS + s] = (s >= c) ? 1.f : 0.f;
    }
}

#define REC_SMEM ((12288 + 8192 + 16384 + 16384 + 3072 + 1536) * (int)sizeof(float))

extern "C" void kernel_launch(void* const* d_in, const int* in_sizes, int n_in,
                              void* d_out, int out_size)
{
    const float* enc   = (const float*)d_in[0];
    const float* tgt   = (const float*)d_in[1];
    const int*   dur   = (const int*)  d_in[2];
    const float* W_pre = (const float*)d_in[3];
    const float* b_pre = (const float*)d_in[4];
    const float* Wih0  = (const float*)d_in[5];
    const float* Whh0  = (const float*)d_in[6];
    const float* bih0  = (const float*)d_in[7];
    const float* bhh0  = (const float*)d_in[8];
    const float* Wih1  = (const float*)d_in[9];
    const float* Whh1  = (const float*)d_in[10];
    const float* bih1  = (const float*)d_in[11];
    const float* bhh1  = (const float*)d_in[12];
    const float* Wpi   = (const float*)d_in[13];
    const float* bpi   = (const float*)d_in[14];
    const float* Wsg   = (const float*)d_in[15];
    const float* bsg   = (const float*)d_in[16];
    const float* Wmu   = (const float*)d_in[17];
    const float* bmu   = (const float*)d_in[18];
    float* out = (float*)d_out;

    init_kernel<<<128, 256>>>();
    prenet_kernel<<<(BB*SS*DOO + 255)/256, 256>>>(tgt, W_pre, b_pre);

    dim3 g2(2, 12, SS);
    gi0_gemm<<<g2, 256>>>(enc, Wih0, bih0);

    cudaFuncSetAttribute(rec_kernel, cudaFuncAttributeMaxDynamicSharedMemorySize, REC_SMEM);
    rec_kernel<<<NCTA, TPB, REC_SMEM>>>(Whh0, bhh0, Wih1, bih1, Whh1, bhh1);

    dim3 g4(2, SS);
    out_gemm<<<g4, 256>>>(enc, Wpi, bpi, Wsg, bsg, Wmu, bmu, out);

    tail_kernel<<<1024 + BB, 256>>>(tgt, dur, out);
}

// round 12
// speedup vs baseline: 1.0965x; 1.0965x over previous
#include <cuda_runtime.h>
#include <math.h>

#define BB   128
#define SS   512
#define CC   256
#define DOO  4
#define GG   10
#define NCTA 128
#define TPB  512

#define OUT_PI   (BB*SS*DOO)
#define OUT_SG   (OUT_PI + BB*SS*GG)
#define OUT_MU   (OUT_SG + BB*SS*GG*DOO)
#define OUT_MASK (OUT_MU + BB*SS*GG*DOO)

__device__ float g_pn[BB*SS*DOO];
__device__ float g_gi0[(size_t)SS*768*BB];
__device__ float g_h0[2][256*BB];
__device__ float g_h1[2][256*BB];
__device__ float g_H[(size_t)SS*256*BB];
__device__ unsigned int g_flag[4][64];     // [stream = pr*2+half][ug]

__device__ __forceinline__ float sigmoidf_(float x){ return 1.f/(1.f + expf(-x)); }
__device__ __forceinline__ void ffma2(unsigned long long &acc,
                                      unsigned long long a, unsigned long long b){
    asm("fma.rn.f32x2 %0, %1, %2, %0;" : "+l"(acc) : "l"(a), "l"(b));
}
__device__ __forceinline__ float2 u2f2(unsigned long long v){
    float2 f; asm("mov.b64 {%0,%1}, %2;" : "=f"(f.x), "=f"(f.y) : "l"(v)); return f;
}

__global__ void init_kernel(){
    int i = blockIdx.x*256 + threadIdx.x;
    if (i < 256) ((unsigned int*)g_flag)[i] = 0u;
    g_h0[0][i] = 0.f; g_h0[1][i] = 0.f;
    g_h1[0][i] = 0.f; g_h1[1][i] = 0.f;
}

__global__ void prenet_kernel(const float* __restrict__ tgt,
                              const float* __restrict__ W_pre,
                              const float* __restrict__ b_pre){
    int idx = blockIdx.x*256 + threadIdx.x;
    if (idx >= BB*SS*DOO) return;
    int d = idx & 3, s = (idx >> 2) & (SS-1), b = idx >> 11;
    float v = b_pre[d];
    if (s > 0){
        const float* pv = tgt + ((size_t)(b*SS + s - 1))*DOO;
        #pragma unroll
        for (int e = 0; e < 4; e++) v += pv[e]*W_pre[d*DOO + e];
    }
    g_pn[idx] = v;
}

__global__ __launch_bounds__(256) void gi0_gemm(const float* __restrict__ enc,
                                                const float* __restrict__ Wih0,
                                                const float* __restrict__ bih0){
    __shared__ float As[32][68];
    __shared__ float Wd[32][132];
    const int s  = blockIdx.z, c0 = blockIdx.y*64, b0 = blockIdx.x*64;
    const int t  = threadIdx.x, bg = t & 15, cg = t >> 4;
    unsigned long long acc[4][2];
    #pragma unroll
    for (int i = 0; i < 4; i++){ acc[i][0] = 0ULL; acc[i][1] = 0ULL; }

    for (int kk = 0; kk < 260; kk += 32){
        for (int i = t; i < 512; i += 256){
            int b = i >> 3, kq = i & 7, kg = kk + kq*4;
            float4 v = make_float4(0.f,0.f,0.f,0.f);
            if (kg < 256)       v = *(const float4*)&enc[(((size_t)(b0+b))*SS + s)*CC + kg];
            else if (kg == 256) v = *(const float4*)&g_pn[(((size_t)(b0+b))*SS + s)*DOO];
            int k = kq*4;
            As[k][b] = v.x; As[k+1][b] = v.y; As[k+2][b] = v.z; As[k+3][b] = v.w;
        }
        for (int i = t; i < 512; i += 256){
            int c = i >> 3, kq = i & 7, kg = kk + kq*4;
            float4 v = make_float4(0.f,0.f,0.f,0.f);
            if (kg <= 256) v = *(const float4*)&Wih0[(size_t)(c0+c)*260 + kg];
            int k = kq*4;
            Wd[k][2*c] = v.x;   Wd[k][2*c+1] = v.x;
            Wd[k+1][2*c] = v.y; Wd[k+1][2*c+1] = v.y;
            Wd[k+2][2*c] = v.z; Wd[k+2][2*c+1] = v.z;
            Wd[k+3][2*c] = v.w; Wd[k+3][2*c+1] = v.w;
        }
        __syncthreads();
        #pragma unroll 8
        for (int k = 0; k < 32; k++){
            ulonglong2 a   = *(const ulonglong2*)&As[k][bg*4];
            ulonglong2 w01 = *(const ulonglong2*)&Wd[k][cg*8];
            ulonglong2 w23 = *(const ulonglong2*)&Wd[k][cg*8+4];
            ffma2(acc[0][0], a.x, w01.x); ffma2(acc[0][1], a.y, w01.x);
            ffma2(acc[1][0], a.x, w01.y); ffma2(acc[1][1], a.y, w01.y);
            ffma2(acc[2][0], a.x, w23.x); ffma2(acc[2][1], a.y, w23.x);
            ffma2(acc[3][0], a.x, w23.y); ffma2(acc[3][1], a.y, w23.y);
        }
        __syncthreads();
    }
    #pragma unroll
    for (int ci = 0; ci < 4; ci++){
        int c = c0 + cg*4 + ci;
        float bias = bih0[c];
        float2 p0 = u2f2(acc[ci][0]), p1 = u2f2(acc[ci][1]);
        *(float4*)&g_gi0[((size_t)s*768 + c)*BB + b0 + bg*4] =
            make_float4(p0.x+bias, p0.y+bias, p1.x+bias, p1.y+bias);
    }
}

// persistent GRU recurrence: two INDEPENDENT half-CTAs (8 warps, 32 batches each).
// No intra-CTA sync between halves — half X's barrier/poll bubble is hidden by
// half Y's compute. Per half: 6 A-warps (rows 0-23: gh0+gi1, hs0) + 2 B-warps
// (rows gh1, hs1), each warp one k-half. B-warps on different SMSPs per half.
__global__ void __launch_bounds__(TPB, 1) rec_kernel(
    const float* __restrict__ Whh0, const float* __restrict__ bhh0,
    const float* __restrict__ Wih1, const float* __restrict__ bih1,
    const float* __restrict__ Whh1, const float* __restrict__ bhh1)
{
    extern __shared__ float sm[];
    float* wqA = sm;                 // 12288 : A rows 0-23 [r3][k][16 dup-pairs]
    float* wBq = wqA + 12288;        // 8192  : B rows [k][32: 4sg x 3 dup-pairs+pad]
    float* hs0 = wBq + 8192;         // 16384 : per-half 8192 = 256u x 32b
    float* hs1 = hs0 + 16384;        // 16384
    float* pA  = hs1 + 16384;        // 3072  : per-half 2kh x 24r x 32b
    float* pB  = pA + 3072;          // 1536  : per-half 2kh x 12r x 32b

    const int t = threadIdx.x, w = t >> 5, l = t & 31;
    const int half = t >> 8, hw = w & 7, ht = t & 255;
    const int ug = blockIdx.x >> 1, pr = blockIdx.x & 1;
    const int u0 = ug*4;
    const int strm = pr*2 + half;
    const int b0s = pr*64 + half*32;
    float* hs0h = hs0 + half*8192;
    float* hs1h = hs1 + half*8192;
    float* pAh  = pA + half*1536;
    float* pBh  = pB + half*768;
    const unsigned int* fl = g_flag[strm];

    for (int i = t; i < 24*256; i += TPB){
        int row = i >> 8, k = i & 255;
        int g3 = row/12, rr = row - g3*12;
        int ui2 = rr/3, g = rr - ui2*3;
        const float* W = (g3 == 0) ? Whh0 : Wih1;
        float v = W[(size_t)(g*256 + u0 + ui2)*256 + k];
        int off = (row >> 3)*4096 + k*16 + (row & 7)*2;
        wqA[off] = v; wqA[off+1] = v;
    }
    for (int i = t; i < 12*256; i += TPB){
        int row = i >> 8, k = i & 255;
        int ui2 = row/3, g = row - ui2*3;
        float v = Whh1[(size_t)(g*256 + u0 + ui2)*256 + k];
        int off = k*32 + ui2*8 + (row - ui2*3)*2;
        wBq[off] = v; wBq[off+1] = v;
    }

    // warp roles (B-warps on distinct SMSPs per half)
    bool isB; int kh, r3 = 0;
    if (half == 0){
        isB = (hw >= 6);
        if (isB) kh = hw - 6; else { r3 = hw >> 1; kh = hw & 1; }
    } else {
        isB = (hw == 4 || hw == 5);
        if (isB) kh = hw - 4;
        else { int a = (hw < 4) ? hw : hw - 2; r3 = a >> 1; kh = a & 1; }
    }
    const int sg = l >> 3, lb = l & 7;

    // update-thread constants
    const int uui = (ht & 127) >> 5, ubl = ht & 31, uu = u0 + uui;
    float b0r=0,b0z=0,b0n=0,b1ir=0,b1iz=0,b1in=0,b1hr=0,b1hz=0,b1hn=0;
    if (ht < 128){
        b0r=bhh0[uu]; b0z=bhh0[256+uu]; b0n=bhh0[512+uu];
    } else {
        b1ir=bih1[uu]; b1iz=bih1[256+uu]; b1in=bih1[512+uu];
        b1hr=bhh1[uu]; b1hz=bhh1[256+uu]; b1hn=bhh1[512+uu];
    }
    __syncthreads();   // weights ready (once, before loop)

    for (int ph = 0; ph < 513; ph++){
        const float* src0 = g_h0[(ph+1) & 1];
        const float* src1 = g_h1[ph & 1];
        float* dst0 = g_h0[ph & 1];
        float* dst1 = g_h1[(ph+1) & 1];

        // poll all 64 producer flags of this stream (warp 0 of half)
        if (hw == 0){
            bool ok;
            do {
                unsigned int m = 0xffffffffu;
                if (l < 16){
                    unsigned int a,b,c,d;
                    asm volatile("ld.volatile.global.v4.u32 {%0,%1,%2,%3}, [%4];"
                                 : "=r"(a), "=r"(b), "=r"(c), "=r"(d) : "l"(fl + l*4));
                    m = min(min(a,b), min(c,d));
                }
                ok = __all_sync(0xffffffffu, m >= (unsigned int)ph);
            } while (!ok);
            __threadfence();
        }
        asm volatile("bar.sync %0, 256;" :: "r"(1 + half) : "memory");

        // prefetch update inputs
        float gir=0.f, giz=0.f, gin=0.f, hold=0.f;
        if (ht < 128){
            hold = __ldcg(&src0[uu*BB + b0s + ubl]);
            if (ph < 512){
                const float* gb = g_gi0 + (size_t)ph*768*BB;
                gir = __ldcg(&gb[(size_t)uu*BB       + b0s + ubl]);
                giz = __ldcg(&gb[(size_t)(256+uu)*BB + b0s + ubl]);
                gin = __ldcg(&gb[(size_t)(512+uu)*BB + b0s + ubl]);
            }
        } else {
            hold = __ldcg(&src1[uu*BB + b0s + ubl]);
        }

        // stage this half's 32-batch h tiles
        for (int j = ht; j < 2048; j += 256)
            ((float4*)hs0h)[j] = __ldcg((const float4*)&src0[(j>>3)*BB + b0s + (j&7)*4]);
        for (int j = ht; j < 2048; j += 256)
            ((float4*)hs1h)[j] = __ldcg((const float4*)&src1[(j>>3)*BB + b0s + (j&7)*4]);
        asm volatile("bar.sync %0, 256;" :: "r"(1 + half) : "memory");

        if (!isB){
            const float* hp = hs0h + kh*4096 + lb*4;
            const float* wp = wqA + r3*4096 + kh*2048 + sg*4;
            unsigned long long a00=0,a01=0,a10=0,a11=0;
            #pragma unroll 16
            for (int k = 0; k < 128; k++){
                ulonglong2 hq = *(const ulonglong2*)(hp + k*32);
                ulonglong2 wv = *(const ulonglong2*)(wp + k*16);
                ffma2(a00, hq.x, wv.x); ffma2(a01, hq.y, wv.x);
                ffma2(a10, hq.x, wv.y); ffma2(a11, hq.y, wv.y);
            }
            const int row0 = r3*8 + 2*sg;
            float2 p0, p1;
            p0 = u2f2(a00); p1 = u2f2(a01);
            *(float4*)&pAh[(kh*24 + row0)*32 + lb*4]   = make_float4(p0.x,p0.y,p1.x,p1.y);
            p0 = u2f2(a10); p1 = u2f2(a11);
            *(float4*)&pAh[(kh*24 + row0+1)*32 + lb*4] = make_float4(p0.x,p0.y,p1.x,p1.y);
        } else {
            const float* hp = hs1h + kh*4096 + lb*4;
            const float* wp = wBq + kh*4096 + sg*8;
            unsigned long long c00=0,c01=0,c10=0,c11=0,c20=0,c21=0;
            #pragma unroll 16
            for (int k = 0; k < 128; k++){
                ulonglong2 hq = *(const ulonglong2*)(hp + k*32);
                ulonglong2 wv = *(const ulonglong2*)(wp + k*32);
                unsigned long long w2 = *(const unsigned long long*)(wp + k*32 + 4);
                ffma2(c00, hq.x, wv.x); ffma2(c01, hq.y, wv.x);
                ffma2(c10, hq.x, wv.y); ffma2(c11, hq.y, wv.y);
                ffma2(c20, hq.x, w2);   ffma2(c21, hq.y, w2);
            }
            const int rb = kh*12 + sg*3;
            float2 p0, p1;
            p0 = u2f2(c00); p1 = u2f2(c01);
            *(float4*)&pBh[(rb+0)*32 + lb*4] = make_float4(p0.x,p0.y,p1.x,p1.y);
            p0 = u2f2(c10); p1 = u2f2(c11);
            *(float4*)&pBh[(rb+1)*32 + lb*4] = make_float4(p0.x,p0.y,p1.x,p1.y);
            p0 = u2f2(c20); p1 = u2f2(c21);
            *(float4*)&pBh[(rb+2)*32 + lb*4] = make_float4(p0.x,p0.y,p1.x,p1.y);
        }
        asm volatile("bar.sync %0, 256;" :: "r"(1 + half) : "memory");

        if (ht < 128){
            if (ph < 512){
                int r0 = uui*3;
                float s0 = pAh[r0*32+ubl]     + pAh[(24+r0)*32+ubl];
                float s1 = pAh[(r0+1)*32+ubl] + pAh[(24+r0+1)*32+ubl];
                float s2 = pAh[(r0+2)*32+ubl] + pAh[(24+r0+2)*32+ubl];
                float r = sigmoidf_(gir + s0 + b0r);
                float z = sigmoidf_(giz + s1 + b0z);
                float n = tanhf(gin + r*(s2 + b0n));
                dst0[uu*BB + b0s + ubl] = 0.1f*hold + 0.9f*((1.f - z)*n + z*hold);
            }
        } else {
            if (ph >= 1){
                int r0 = uui*3, q0 = 12 + r0;
                float i0 = pAh[q0*32+ubl]     + pAh[(24+q0)*32+ubl]   + b1ir;
                float i1 = pAh[(q0+1)*32+ubl] + pAh[(24+q0+1)*32+ubl] + b1iz;
                float i2 = pAh[(q0+2)*32+ubl] + pAh[(24+q0+2)*32+ubl] + b1in;
                float hg0 = pBh[r0*32+ubl]     + pBh[(12+r0)*32+ubl]   + b1hr;
                float hg1 = pBh[(r0+1)*32+ubl] + pBh[(12+r0+1)*32+ubl] + b1hz;
                float hg2 = pBh[(r0+2)*32+ubl] + pBh[(12+r0+2)*32+ubl] + b1hn;
                float r = sigmoidf_(i0 + hg0);
                float z = sigmoidf_(i1 + hg1);
                float n = tanhf(i2 + r*hg2);
                float hout = 0.1f*hold + 0.9f*((1.f - z)*n + z*hold);
                dst1[uu*BB + b0s + ubl] = hout;
                g_H[((size_t)(ph-1)*256 + uu)*BB + b0s + ubl] = hout;
            }
        }
        asm volatile("bar.sync %0, 256;" :: "r"(1 + half) : "memory");
        if (ht == 0){
            __threadfence();
            *(volatile unsigned int*)&g_flag[strm][ug] = (unsigned int)(ph+1);
        }
    }
}

__global__ __launch_bounds__(256) void out_gemm(const float* __restrict__ enc,
    const float* __restrict__ Wpi, const float* __restrict__ bpi,
    const float* __restrict__ Wsg, const float* __restrict__ bsg,
    const float* __restrict__ Wmu, const float* __restrict__ bmu,
    float* __restrict__ out)
{
    __shared__ float As[32][68];
    __shared__ float Wd[32][196];
    __shared__ float Rs[64][96];
    const int s  = blockIdx.y, b0 = blockIdx.x*64;
    const int t  = threadIdx.x, bg = t & 15, cg = t >> 4;
    unsigned long long acc[6][2];
    #pragma unroll
    for (int i = 0; i < 6; i++){ acc[i][0] = 0ULL; acc[i][1] = 0ULL; }

    for (int kk = 0; kk < 512; kk += 32){
        if (kk < 256){
            for (int i = t; i < 2048; i += 256){
                int k = i >> 6, b = i & 63;
                As[k][b] = g_H[((size_t)s*256 + kk + k)*BB + b0 + b];
            }
        } else {
            for (int i = t; i < 512; i += 256){
                int b = i >> 3, kq = i & 7, kg = kk - 256 + kq*4;
                float4 v = *(const float4*)&enc[(((size_t)(b0+b))*SS + s)*CC + kg];
                int k = kq*4;
                As[k][b] = v.x; As[k+1][b] = v.y; As[k+2][b] = v.z; As[k+3][b] = v.w;
            }
        }
        for (int i = t; i < 768; i += 256){
            int c = i >> 3, kq = i & 7, kg = kk + kq*4;
            float4 v = make_float4(0.f,0.f,0.f,0.f);
            if      (c < 10) v = *(const float4*)&Wpi[(size_t)c*512 + kg];
            else if (c < 50) v = *(const float4*)&Wsg[(size_t)(c-10)*512 + kg];
            else if (c < 90) v = *(const float4*)&Wmu[(size_t)(c-50)*512 + kg];
            int k = kq*4;
            Wd[k][2*c] = v.x;   Wd[k][2*c+1] = v.x;
            Wd[k+1][2*c] = v.y; Wd[k+1][2*c+1] = v.y;
            Wd[k+2][2*c] = v.z; Wd[k+2][2*c+1] = v.z;
            Wd[k+3][2*c] = v.w; Wd[k+3][2*c+1] = v.w;
        }
        __syncthreads();
        #pragma unroll 4
        for (int k = 0; k < 32; k++){
            ulonglong2 a   = *(const ulonglong2*)&As[k][bg*4];
            ulonglong2 w01 = *(const ulonglong2*)&Wd[k][cg*12];
            ulonglong2 w23 = *(const ulonglong2*)&Wd[k][cg*12+4];
            ulonglong2 w45 = *(const ulonglong2*)&Wd[k][cg*12+8];
            ffma2(acc[0][0], a.x, w01.x); ffma2(acc[0][1], a.y, w01.x);
            ffma2(acc[1][0], a.x, w01.y); ffma2(acc[1][1], a.y, w01.y);
            ffma2(acc[2][0], a.x, w23.x); ffma2(acc[2][1], a.y, w23.x);
            ffma2(acc[3][0], a.x, w23.y); ffma2(acc[3][1], a.y, w23.y);
            ffma2(acc[4][0], a.x, w45.x); ffma2(acc[4][1], a.y, w45.x);
            ffma2(acc[5][0], a.x, w45.y); ffma2(acc[5][1], a.y, w45.y);
        }
        __syncthreads();
    }
    #pragma unroll
    for (int ci = 0; ci < 6; ci++){
        int c = cg*6 + ci;
        float bias = (c < 10) ? bpi[c] : (c < 50) ? bsg[c-10] : (c < 90) ? bmu[c-50] : 0.f;
        float2 p0 = u2f2(acc[ci][0]), p1 = u2f2(acc[ci][1]);
        Rs[bg*4+0][c] = p0.x + bias;
        Rs[bg*4+1][c] = p0.y + bias;
        Rs[bg*4+2][c] = p1.x + bias;
        Rs[bg*4+3][c] = p1.y + bias;
    }
    __syncthreads();

    if (t < 64){
        int b = b0 + t;
        float lv[10]; float m = -1e30f;
        #pragma unroll
        for (int g = 0; g < 10; g++){ lv[g] = Rs[t][g]; m = fmaxf(m, lv[g]); }
        float sum = 0.f;
        #pragma unroll
        for (int g = 0; g < 10; g++){ lv[g] = expf(lv[g]-m); sum += lv[g]; }
        float inv = 1.f/sum;
        size_t base = (size_t)OUT_PI + ((size_t)b*SS + s)*10;
        #pragma unroll
        for (int g = 0; g < 10; g++) out[base + g] = lv[g]*inv;
    }
    for (int i = t; i < 64*40; i += 256){
        int row = i/40, j = i - row*40, b = b0 + row;
        float x  = Rs[row][10+j];
        float xm = Rs[row][50+j];
        size_t base = ((size_t)b*SS + s)*40 + j;
        out[(size_t)OUT_SG + base] = (x > 0.f) ? (x + 1.f) : expf(x);
        out[(size_t)OUT_MU + base] = xm;
    }
}

__global__ void tail_kernel(const float* __restrict__ tgt,
                            const int* __restrict__ dur,
                            float* __restrict__ out){
    if (blockIdx.x < 1024){
        int idx = blockIdx.x*256 + threadIdx.x;
        out[idx] = tgt[idx];
    } else {
        int b = blockIdx.x - 1024;
        __shared__ int cnt;
        if (threadIdx.x == 0) cnt = 0;
        __syncthreads();
        int local = 0;
        for (int s = threadIdx.x; s < SS; s += 256) local += (dur[b*SS + s] > 0) ? 1 : 0;
        #pragma unroll
        for (int o = 16; o; o >>= 1) local += __shfl_down_sync(0xffffffffu, local, o);
        if ((threadIdx.x & 31) == 0) atomicAdd(&cnt, local);
        __syncthreads();
        int c = cnt;
        for (int s = threadIdx.x; s < SS; s += 256)
            out[OUT_MASK + b*SS + s] = (s >= c) ? 1.f : 0.f;
    }
}

#define REC_SMEM ((12288 + 8192 + 16384 + 16384 + 3072 + 1536) * (int)sizeof(float))

extern "C" void kernel_launch(void* const* d_in, const int* in_sizes, int n_in,
                              void* d_out, int out_size)
{
    const float* enc   = (const float*)d_in[0];
    const float* tgt   = (const float*)d_in[1];
    const int*   dur   = (const int*)  d_in[2];
    const float* W_pre = (const float*)d_in[3];
    const float* b_pre = (const float*)d_in[4];
    const float* Wih0  = (const float*)d_in[5];
    const float* Whh0  = (const float*)d_in[6];
    const float* bih0  = (const float*)d_in[7];
    const float* bhh0  = (const float*)d_in[8];
    const float* Wih1  = (const float*)d_in[9];
    const float* Whh1  = (const float*)d_in[10];
    const float* bih1  = (const float*)d_in[11];
    const float* bhh1  = (const float*)d_in[12];
    const float* Wpi   = (const float*)d_in[13];
    const float* bpi   = (const float*)d_in[14];
    const float* Wsg   = (const float*)d_in[15];
    const float* bsg   = (const float*)d_in[16];
    const float* Wmu   = (const float*)d_in[17];
    const float* bmu   = (const float*)d_in[18];
    float* out = (float*)d_out;

    init_kernel<<<128, 256>>>();
    prenet_kernel<<<(BB*SS*DOO + 255)/256, 256>>>(tgt, W_pre, b_pre);

    dim3 g2(2, 12, SS);
    gi0_gemm<<<g2, 256>>>(enc, Wih0, bih0);

    cudaFuncSetAttribute(rec_kernel, cudaFuncAttributeMaxDynamicSharedMemorySize, REC_SMEM);
    rec_kernel<<<NCTA, TPB, REC_SMEM>>>(Whh0, bhh0, Wih1, bih1, Whh1, bhh1);

    dim3 g4(2, SS);
    out_gemm<<<g4, 256>>>(enc, Wpi, bpi, Wsg, bsg, Wmu, bmu, out);

    tail_kernel<<<1024 + BB, 256>>>(tgt, dur, out);
}

// round 13
// speedup vs baseline: 1.3763x; 1.2552x over previous
#include <cuda_runtime.h>
#include <math.h>

#define BB   128
#define SS   512
#define CC   256
#define DOO  4
#define GG   10
#define NCTA 128
#define TPB  512

#define OUT_PI   (BB*SS*DOO)
#define OUT_SG   (OUT_PI + BB*SS*GG)
#define OUT_MU   (OUT_SG + BB*SS*GG*DOO)
#define OUT_MASK (OUT_MU + BB*SS*GG*DOO)

__device__ float g_pn[BB*SS*DOO];
__device__ float g_gi0[(size_t)SS*768*BB];
__device__ float g_h0[2][256*BB];
__device__ float g_h1[2][256*BB];
__device__ float g_H[(size_t)SS*256*BB];
__device__ __align__(16) unsigned int g_f0[2][64];   // h0-ready flags [bh][ug]
__device__ __align__(16) unsigned int g_f1[2][64];   // h1-ready flags [bh][ug]

__device__ __forceinline__ float sigmoidf_(float x){ return 1.f/(1.f + expf(-x)); }
__device__ __forceinline__ void ffma2(unsigned long long &acc,
                                      unsigned long long a, unsigned long long b){
    asm("fma.rn.f32x2 %0, %1, %2, %0;" : "+l"(acc) : "l"(a), "l"(b));
}
__device__ __forceinline__ float2 u2f2(unsigned long long v){
    float2 f; asm("mov.b64 {%0,%1}, %2;" : "=f"(f.x), "=f"(f.y) : "l"(v)); return f;
}
// one warp polls 64 flags (16 lanes x v4) until all >= tgt, then fences
__device__ __forceinline__ void pollwarp(const unsigned int* f, int l, unsigned int tgt){
    bool ok;
    do {
        unsigned int m = 0xffffffffu;
        if (l < 16){
            unsigned int a,b,c,d;
            asm volatile("ld.volatile.global.v4.u32 {%0,%1,%2,%3}, [%4];"
                         : "=r"(a), "=r"(b), "=r"(c), "=r"(d) : "l"(f + l*4));
            m = min(min(a,b), min(c,d));
        }
        ok = __all_sync(0xffffffffu, m >= tgt);
    } while (!ok);
    __threadfence();
}

__global__ void init_kernel(){
    int i = blockIdx.x*256 + threadIdx.x;
    if (i < 128){ ((unsigned int*)g_f0)[i] = 0u; ((unsigned int*)g_f1)[i] = 0u; }
    g_h0[0][i] = 0.f; g_h0[1][i] = 0.f;
    g_h1[0][i] = 0.f; g_h1[1][i] = 0.f;
}

__global__ void prenet_kernel(const float* __restrict__ tgt,
                              const float* __restrict__ W_pre,
                              const float* __restrict__ b_pre){
    int idx = blockIdx.x*256 + threadIdx.x;
    if (idx >= BB*SS*DOO) return;
    int d = idx & 3, s = (idx >> 2) & (SS-1), b = idx >> 11;
    float v = b_pre[d];
    if (s > 0){
        const float* pv = tgt + ((size_t)(b*SS + s - 1))*DOO;
        #pragma unroll
        for (int e = 0; e < 4; e++) v += pv[e]*W_pre[d*DOO + e];
    }
    g_pn[idx] = v;
}

__global__ __launch_bounds__(256) void gi0_gemm(const float* __restrict__ enc,
                                                const float* __restrict__ Wih0,
                                                const float* __restrict__ bih0){
    __shared__ float As[32][68];
    __shared__ float Wd[32][132];
    const int s  = blockIdx.z, c0 = blockIdx.y*64, b0 = blockIdx.x*64;
    const int t  = threadIdx.x, bg = t & 15, cg = t >> 4;
    unsigned long long acc[4][2];
    #pragma unroll
    for (int i = 0; i < 4; i++){ acc[i][0] = 0ULL; acc[i][1] = 0ULL; }

    for (int kk = 0; kk < 260; kk += 32){
        for (int i = t; i < 512; i += 256){
            int b = i >> 3, kq = i & 7, kg = kk + kq*4;
            float4 v = make_float4(0.f,0.f,0.f,0.f);
            if (kg < 256)       v = *(const float4*)&enc[(((size_t)(b0+b))*SS + s)*CC + kg];
            else if (kg == 256) v = *(const float4*)&g_pn[(((size_t)(b0+b))*SS + s)*DOO];
            int k = kq*4;
            As[k][b] = v.x; As[k+1][b] = v.y; As[k+2][b] = v.z; As[k+3][b] = v.w;
        }
        for (int i = t; i < 512; i += 256){
            int c = i >> 3, kq = i & 7, kg = kk + kq*4;
            float4 v = make_float4(0.f,0.f,0.f,0.f);
            if (kg <= 256) v = *(const float4*)&Wih0[(size_t)(c0+c)*260 + kg];
            int k = kq*4;
            Wd[k][2*c] = v.x;   Wd[k][2*c+1] = v.x;
            Wd[k+1][2*c] = v.y; Wd[k+1][2*c+1] = v.y;
            Wd[k+2][2*c] = v.z; Wd[k+2][2*c+1] = v.z;
            Wd[k+3][2*c] = v.w; Wd[k+3][2*c+1] = v.w;
        }
        __syncthreads();
        #pragma unroll 8
        for (int k = 0; k < 32; k++){
            ulonglong2 a   = *(const ulonglong2*)&As[k][bg*4];
            ulonglong2 w01 = *(const ulonglong2*)&Wd[k][cg*8];
            ulonglong2 w23 = *(const ulonglong2*)&Wd[k][cg*8+4];
            ffma2(acc[0][0], a.x, w01.x); ffma2(acc[0][1], a.y, w01.x);
            ffma2(acc[1][0], a.x, w01.y); ffma2(acc[1][1], a.y, w01.y);
            ffma2(acc[2][0], a.x, w23.x); ffma2(acc[2][1], a.y, w23.x);
            ffma2(acc[3][0], a.x, w23.y); ffma2(acc[3][1], a.y, w23.y);
        }
        __syncthreads();
    }
    #pragma unroll
    for (int ci = 0; ci < 4; ci++){
        int c = c0 + cg*4 + ci;
        float bias = bih0[c];
        float2 p0 = u2f2(acc[ci][0]), p1 = u2f2(acc[ci][1]);
        *(float4*)&g_gi0[((size_t)s*768 + c)*BB + b0 + bg*4] =
            make_float4(p0.x+bias, p0.y+bias, p1.x+bias, p1.y+bias);
    }
}

// persistent GRU recurrence — round-8 work layout, split-flag sync.
// Group A (warps 0-11): rows 0-23 (gh0, gi1) on hs0; quarter staging bars 1-4.
// Group B (warps 12-15): rows gh1 on hs1; staging bars 9/10, reduce bar 11.
// GRU0 update: warps 0-7 (bar 8) -> f0.  GRU1 update: warps 8-15 (bar 12) -> f1.
__global__ void __launch_bounds__(TPB, 1) rec_kernel(
    const float* __restrict__ Whh0, const float* __restrict__ bhh0,
    const float* __restrict__ Wih1, const float* __restrict__ bih1,
    const float* __restrict__ Whh1, const float* __restrict__ bhh1)
{
    extern __shared__ float sm[];
    float* wqA = sm;                 // 12288
    float* wBd = wqA + 12288;        // 6144
    float* hs0 = wBd + 6144;         // 16384
    float* hs1 = hs0 + 16384;        // 16384
    float* pA  = hs1 + 16384;        // 6144
    float* pC  = pA + 6144;          // 768

    const int t = threadIdx.x, w = t >> 5, l = t & 31;
    const int ug = blockIdx.x >> 1, bh = blockIdx.x & 1;
    const int u0 = ug*4, b0 = bh*64;

    for (int i = t; i < 24*256; i += TPB){
        int row = i >> 8, k = i & 255;
        int g3 = row/12, rr = row - g3*12;
        int ui2 = rr/3, g = rr - ui2*3;
        const float* W = (g3 == 0) ? Whh0 : Wih1;
        float v = W[(size_t)(g*256 + u0 + ui2)*256 + k];
        int r3 = row >> 3, s = row & 7;
        int off = r3*4096 + k*16 + (s >> 2)*8 + (s & 3)*2;
        wqA[off] = v; wqA[off+1] = v;
    }
    for (int i = t; i < 12*256; i += TPB){
        int row = i >> 8, k = i & 255;
        int ui2 = row/3, g = row - ui2*3;
        float v = Whh1[(size_t)(g*256 + u0 + ui2)*256 + k];
        wBd[row*512 + 2*k]   = v;
        wBd[row*512 + 2*k+1] = v;
    }

    // update roles: t<256 -> GRU0 item (ui,bl); t>=256 -> GRU1 item
    const int ti = (t < 256) ? t : (t - 256);
    const int ui = ti >> 6, bl = ti & 63, u = u0 + ui;
    float b0r=0,b0z=0,b0n=0,b1ir=0,b1iz=0,b1in=0,b1hr=0,b1hz=0,b1hn=0;
    if (t < 256){
        b0r=bhh0[u]; b0z=bhh0[256+u]; b0n=bhh0[512+u];
    } else {
        b1ir=bih1[u]; b1iz=bih1[256+u]; b1in=bih1[512+u];
        b1hr=bhh1[u]; b1hz=bhh1[256+u]; b1hn=bhh1[512+u];
    }
    __syncthreads();

    for (int ph = 0; ph < 513; ph++){
        const float* src0 = g_h0[(ph+1) & 1];
        const float* src1 = g_h1[ph & 1];
        float* dst0 = g_h0[ph & 1];
        float* dst1 = g_h1[(ph+1) & 1];

        if (w == 0)  pollwarp(g_f0[bh], l, (unsigned int)ph);
        if (w == 12) pollwarp(g_f1[bh], l, (unsigned int)ph);

        if (w < 12){
            asm volatile("bar.sync 5, 384;" ::: "memory");

            float gir=0.f, giz=0.f, gin=0.f, hold0=0.f;
            if (t < 256){
                hold0 = __ldcg(&src0[u*BB + b0 + bl]);
                if (ph < 512){
                    const float* gb = g_gi0 + (size_t)ph*768*BB;
                    gir = __ldcg(&gb[(size_t)u*BB       + b0 + bl]);
                    giz = __ldcg(&gb[(size_t)(256+u)*BB + b0 + bl]);
                    gin = __ldcg(&gb[(size_t)(512+u)*BB + b0 + bl]);
                }
            }

            const int q = w & 3, r3 = w >> 2;
            for (int i = (r3 << 5) + l; i < 1024; i += 96){
                ((float4*)hs0)[(q << 10) + i] =
                    __ldcg((const float4*)&src0[((q << 6) + (i >> 4))*BB + b0 + (i & 15)*4]);
            }
            asm volatile("bar.sync %0, 96;" :: "r"(1 + q) : "memory");

            const int half = l >> 4, lb = l & 15;
            const float* hp = hs0 + q*4096 + lb*4;
            const float* wp = wqA + r3*4096 + q*1024 + half*8;
            unsigned long long a00=0,a01=0,a10=0,a11=0,a20=0,a21=0,a30=0,a31=0;
            #pragma unroll 4
            for (int k = 0; k < 64; k++){
                ulonglong2 hq = *(const ulonglong2*)(hp + k*64);
                ulonglong2 wA_ = *(const ulonglong2*)(wp + k*16);
                ulonglong2 wB_ = *(const ulonglong2*)(wp + k*16 + 4);
                ffma2(a00, hq.x, wA_.x); ffma2(a01, hq.y, wA_.x);
                ffma2(a10, hq.x, wA_.y); ffma2(a11, hq.y, wA_.y);
                ffma2(a20, hq.x, wB_.x); ffma2(a21, hq.y, wB_.x);
                ffma2(a30, hq.x, wB_.y); ffma2(a31, hq.y, wB_.y);
            }
            const int rowbase = q*24 + r3*8 + half*4;
            {
                float2 p0, p1;
                p0 = u2f2(a00); p1 = u2f2(a01);
                *(float4*)&pA[(rowbase+0)*64 + lb*4] = make_float4(p0.x,p0.y,p1.x,p1.y);
                p0 = u2f2(a10); p1 = u2f2(a11);
                *(float4*)&pA[(rowbase+1)*64 + lb*4] = make_float4(p0.x,p0.y,p1.x,p1.y);
                p0 = u2f2(a20); p1 = u2f2(a21);
                *(float4*)&pA[(rowbase+2)*64 + lb*4] = make_float4(p0.x,p0.y,p1.x,p1.y);
                p0 = u2f2(a30); p1 = u2f2(a31);
                *(float4*)&pA[(rowbase+3)*64 + lb*4] = make_float4(p0.x,p0.y,p1.x,p1.y);
            }
            asm volatile("bar.sync 7, 384;" ::: "memory");

            if (t < 256 && ph < 512){
                int r0 = ui*3;
                float s0 = pA[r0*64+bl]     + pA[(24+r0)*64+bl]     + pA[(48+r0)*64+bl]     + pA[(72+r0)*64+bl];
                float s1 = pA[(r0+1)*64+bl] + pA[(24+r0+1)*64+bl]   + pA[(48+r0+1)*64+bl]   + pA[(72+r0+1)*64+bl];
                float s2 = pA[(r0+2)*64+bl] + pA[(24+r0+2)*64+bl]   + pA[(48+r0+2)*64+bl]   + pA[(72+r0+2)*64+bl];
                float r = sigmoidf_(gir + s0 + b0r);
                float z = sigmoidf_(giz + s1 + b0z);
                float n = tanhf(gin + r*(s2 + b0n));
                dst0[u*BB + b0 + bl] = 0.1f*hold0 + 0.9f*((1.f - z)*n + z*hold0);
            }
            if (w < 8){
                asm volatile("bar.sync 8, 256;" ::: "memory");
                if (t == 0){
                    __threadfence();
                    *(volatile unsigned int*)&g_f0[bh][ug] = (unsigned int)(ph+1);
                }
            }
        } else {
            asm volatile("bar.sync 6, 128;" ::: "memory");

            const int q2 = w - 12;
            const int hh = q2 >> 1, rg = q2 & 1;
            for (int i = ((w & 1) << 5) + l; i < 2048; i += 64){
                ((float4*)hs1)[(hh << 11) + i] =
                    __ldcg((const float4*)&src1[((hh << 7) + (i >> 4))*BB + b0 + (i & 15)*4]);
            }
            asm volatile("bar.sync %0, 64;" :: "r"(9 + hh) : "memory");

            const int half = l >> 4, lb = l & 15;
            const int rbase = rg*6 + half*3;
            const float* hp = hs1 + hh*(128*64) + lb*4;
            const float* wd = wBd + rbase*512 + hh*256;
            unsigned long long c00=0,c01=0,c10=0,c11=0,c20=0,c21=0;
            #pragma unroll 8
            for (int k2 = 0; k2 < 128; k2 += 2){
                ulonglong2 w0 = *(const ulonglong2*)(wd + 2*k2);
                ulonglong2 w1 = *(const ulonglong2*)(wd + 512  + 2*k2);
                ulonglong2 w2 = *(const ulonglong2*)(wd + 1024 + 2*k2);
                ulonglong2 hq0 = *(const ulonglong2*)(hp + k2*64);
                ulonglong2 hq1 = *(const ulonglong2*)(hp + (k2+1)*64);
                ffma2(c00, hq0.x, w0.x); ffma2(c01, hq0.y, w0.x);
                ffma2(c10, hq0.x, w1.x); ffma2(c11, hq0.y, w1.x);
                ffma2(c20, hq0.x, w2.x); ffma2(c21, hq0.y, w2.x);
                ffma2(c00, hq1.x, w0.y); ffma2(c01, hq1.y, w0.y);
                ffma2(c10, hq1.x, w1.y); ffma2(c11, hq1.y, w1.y);
                ffma2(c20, hq1.x, w2.y); ffma2(c21, hq1.y, w2.y);
            }
            if (hh == 0){
                float2 p0, p1;
                p0 = u2f2(c00); p1 = u2f2(c01);
                *(float4*)&pC[(rbase+0)*64 + lb*4] = make_float4(p0.x,p0.y,p1.x,p1.y);
                p0 = u2f2(c10); p1 = u2f2(c11);
                *(float4*)&pC[(rbase+1)*64 + lb*4] = make_float4(p0.x,p0.y,p1.x,p1.y);
                p0 = u2f2(c20); p1 = u2f2(c21);
                *(float4*)&pC[(rbase+2)*64 + lb*4] = make_float4(p0.x,p0.y,p1.x,p1.y);
            }
            asm volatile("bar.sync 11, 128;" ::: "memory");
            if (hh == 1){
                float2 p0, p1; float4 pr;
                p0 = u2f2(c00); p1 = u2f2(c01);
                pr = *(const float4*)&pC[(rbase+0)*64 + lb*4];
                *(float4*)&pC[(rbase+0)*64 + lb*4] =
                    make_float4(pr.x+p0.x, pr.y+p0.y, pr.z+p1.x, pr.w+p1.y);
                p0 = u2f2(c10); p1 = u2f2(c11);
                pr = *(const float4*)&pC[(rbase+1)*64 + lb*4];
                *(float4*)&pC[(rbase+1)*64 + lb*4] =
                    make_float4(pr.x+p0.x, pr.y+p0.y, pr.z+p1.x, pr.w+p1.y);
                p0 = u2f2(c20); p1 = u2f2(c21);
                pr = *(const float4*)&pC[(rbase+2)*64 + lb*4];
                *(float4*)&pC[(rbase+2)*64 + lb*4] =
                    make_float4(pr.x+p0.x, pr.y+p0.y, pr.z+p1.x, pr.w+p1.y);
            }
        }

        // -------- GRU1 section: warps 8-15 ---------------------------------
        if (w >= 8){
            asm volatile("bar.sync 12, 256;" ::: "memory");   // pA + pC ready
            if (ph >= 1){
                float hold1 = __ldcg(&src1[u*BB + b0 + bl]);
                int r0 = ui*3, q0 = 12 + r0;
                float i0 = pA[q0*64+bl]     + pA[(24+q0)*64+bl]     + pA[(48+q0)*64+bl]     + pA[(72+q0)*64+bl]     + b1ir;
                float i1 = pA[(q0+1)*64+bl] + pA[(24+q0+1)*64+bl]   + pA[(48+q0+1)*64+bl]   + pA[(72+q0+1)*64+bl]   + b1iz;
                float i2 = pA[(q0+2)*64+bl] + pA[(24+q0+2)*64+bl]   + pA[(48+q0+2)*64+bl]   + pA[(72+q0+2)*64+bl]   + b1in;
                float hg0 = pC[r0*64+bl]     + b1hr;
                float hg1 = pC[(r0+1)*64+bl] + b1hz;
                float hg2 = pC[(r0+2)*64+bl] + b1hn;
                float r = sigmoidf_(i0 + hg0);
                float z = sigmoidf_(i1 + hg1);
                float n = tanhf(i2 + r*hg2);
                float hout = 0.1f*hold1 + 0.9f*((1.f - z)*n + z*hold1);
                dst1[u*BB + b0 + bl] = hout;
                g_H[((size_t)(ph-1)*256 + u)*BB + b0 + bl] = hout;
            }
            asm volatile("bar.sync 12, 256;" ::: "memory");
            if (t == 256){
                __threadfence();
                *(volatile unsigned int*)&g_f1[bh][ug] = (unsigned int)(ph+1);
            }
        }
    }
}

__global__ __launch_bounds__(256) void out_gemm(const float* __restrict__ enc,
    const float* __restrict__ Wpi, const float* __restrict__ bpi,
    const float* __restrict__ Wsg, const float* __restrict__ bsg,
    const float* __restrict__ Wmu, const float* __restrict__ bmu,
    float* __restrict__ out)
{
    __shared__ float As[32][68];
    __shared__ float Wd[32][196];
    __shared__ float Rs[64][96];
    const int s  = blockIdx.y, b0 = blockIdx.x*64;
    const int t  = threadIdx.x, bg = t & 15, cg = t >> 4;
    unsigned long long acc[6][2];
    #pragma unroll
    for (int i = 0; i < 6; i++){ acc[i][0] = 0ULL; acc[i][1] = 0ULL; }

    for (int kk = 0; kk < 512; kk += 32){
        if (kk < 256){
            for (int i = t; i < 2048; i += 256){
                int k = i >> 6, b = i & 63;
                As[k][b] = g_H[((size_t)s*256 + kk + k)*BB + b0 + b];
            }
        } else {
            for (int i = t; i < 512; i += 256){
                int b = i >> 3, kq = i & 7, kg = kk - 256 + kq*4;
                float4 v = *(const float4*)&enc[(((size_t)(b0+b))*SS + s)*CC + kg];
                int k = kq*4;
                As[k][b] = v.x; As[k+1][b] = v.y; As[k+2][b] = v.z; As[k+3][b] = v.w;
            }
        }
        for (int i = t; i < 768; i += 256){
            int c = i >> 3, kq = i & 7, kg = kk + kq*4;
            float4 v = make_float4(0.f,0.f,0.f,0.f);
            if      (c < 10) v = *(const float4*)&Wpi[(size_t)c*512 + kg];
            else if (c < 50) v = *(const float4*)&Wsg[(size_t)(c-10)*512 + kg];
            else if (c < 90) v = *(const float4*)&Wmu[(size_t)(c-50)*512 + kg];
            int k = kq*4;
            Wd[k][2*c] = v.x;   Wd[k][2*c+1] = v.x;
            Wd[k+1][2*c] = v.y; Wd[k+1][2*c+1] = v.y;
            Wd[k+2][2*c] = v.z; Wd[k+2][2*c+1] = v.z;
            Wd[k+3][2*c] = v.w; Wd[k+3][2*c+1] = v.w;
        }
        __syncthreads();
        #pragma unroll 4
        for (int k = 0; k < 32; k++){
            ulonglong2 a   = *(const ulonglong2*)&As[k][bg*4];
            ulonglong2 w01 = *(const ulonglong2*)&Wd[k][cg*12];
            ulonglong2 w23 = *(const ulonglong2*)&Wd[k][cg*12+4];
            ulonglong2 w45 = *(const ulonglong2*)&Wd[k][cg*12+8];
            ffma2(acc[0][0], a.x, w01.x); ffma2(acc[0][1], a.y, w01.x);
            ffma2(acc[1][0], a.x, w01.y); ffma2(acc[1][1], a.y, w01.y);
            ffma2(acc[2][0], a.x, w23.x); ffma2(acc[2][1], a.y, w23.x);
            ffma2(acc[3][0], a.x, w23.y); ffma2(acc[3][1], a.y, w23.y);
            ffma2(acc[4][0], a.x, w45.x); ffma2(acc[4][1], a.y, w45.x);
            ffma2(acc[5][0], a.x, w45.y); ffma2(acc[5][1], a.y, w45.y);
        }
        __syncthreads();
    }
    #pragma unroll
    for (int ci = 0; ci < 6; ci++){
        int c = cg*6 + ci;
        float bias = (c < 10) ? bpi[c] : (c < 50) ? bsg[c-10] : (c < 90) ? bmu[c-50] : 0.f;
        float2 p0 = u2f2(acc[ci][0]), p1 = u2f2(acc[ci][1]);
        Rs[bg*4+0][c] = p0.x + bias;
        Rs[bg*4+1][c] = p0.y + bias;
        Rs[bg*4+2][c] = p1.x + bias;
        Rs[bg*4+3][c] = p1.y + bias;
    }
    __syncthreads();

    if (t < 64){
        int b = b0 + t;
        float lv[10]; float m = -1e30f;
        #pragma unroll
        for (int g = 0; g < 10; g++){ lv[g] = Rs[t][g]; m = fmaxf(m, lv[g]); }
        float sum = 0.f;
        #pragma unroll
        for (int g = 0; g < 10; g++){ lv[g] = expf(lv[g]-m); sum += lv[g]; }
        float inv = 1.f/sum;
        size_t base = (size_t)OUT_PI + ((size_t)b*SS + s)*10;
        #pragma unroll
        for (int g = 0; g < 10; g++) out[base + g] = lv[g]*inv;
    }
    for (int i = t; i < 64*40; i += 256){
        int row = i/40, j = i - row*40, b = b0 + row;
        float x  = Rs[row][10+j];
        float xm = Rs[row][50+j];
        size_t base = ((size_t)b*SS + s)*40 + j;
        out[(size_t)OUT_SG + base] = (x > 0.f) ? (x + 1.f) : expf(x);
        out[(size_t)OUT_MU + base] = xm;
    }
}

__global__ void tail_kernel(const float* __restrict__ tgt,
                            const int* __restrict__ dur,
                            float* __restrict__ out){
    if (blockIdx.x < 1024){
        int idx = blockIdx.x*256 + threadIdx.x;
        out[idx] = tgt[idx];
    } else {
        int b = blockIdx.x - 1024;
        __shared__ int cnt;
        if (threadIdx.x == 0) cnt = 0;
        __syncthreads();
        int local = 0;
        for (int s = threadIdx.x; s < SS; s += 256) local += (dur[b*SS + s] > 0) ? 1 : 0;
        #pragma unroll
        for (int o = 16; o; o >>= 1) local += __shfl_down_sync(0xffffffffu, local, o);
        if ((threadIdx.x & 31) == 0) atomicAdd(&cnt, local);
        __syncthreads();
        int c = cnt;
        for (int s = threadIdx.x; s < SS; s += 256)
            out[OUT_MASK + b*SS + s] = (s >= c) ? 1.f : 0.f;
    }
}

#define REC_SMEM ((12288 + 6144 + 16384 + 16384 + 6144 + 768) * (int)sizeof(float))

extern "C" void kernel_launch(void* const* d_in, const int* in_sizes, int n_in,
                              void* d_out, int out_size)
{
    const float* enc   = (const float*)d_in[0];
    const float* tgt   = (const float*)d_in[1];
    const int*   dur   = (const int*)  d_in[2];
    const float* W_pre = (const float*)d_in[3];
    const float* b_pre = (const float*)d_in[4];
    const float* Wih0  = (const float*)d_in[5];
    const float* Whh0  = (const float*)d_in[6];
    const float* bih0  = (const float*)d_in[7];
    const float* bhh0  = (const float*)d_in[8];
    const float* Wih1  = (const float*)d_in[9];
    const float* Whh1  = (const float*)d_in[10];
    const float* bih1  = (const float*)d_in[11];
    const float* bhh1  = (const float*)d_in[12];
    const float* Wpi   = (const float*)d_in[13];
    const float* bpi   = (const float*)d_in[14];
    const float* Wsg   = (const float*)d_in[15];
    const float* bsg   = (const float*)d_in[16];
    const float* Wmu   = (const float*)d_in[17];
    const float* bmu   = (const float*)d_in[18];
    float* out = (float*)d_out;

    init_kernel<<<128, 256>>>();
    prenet_kernel<<<(BB*SS*DOO + 255)/256, 256>>>(tgt, W_pre, b_pre);

    dim3 g2(2, 12, SS);
    gi0_gemm<<<g2, 256>>>(enc, Wih0, bih0);

    cudaFuncSetAttribute(rec_kernel, cudaFuncAttributeMaxDynamicSharedMemorySize, REC_SMEM);
    rec_kernel<<<NCTA, TPB, REC_SMEM>>>(Whh0, bhh0, Wih1, bih1, Whh1, bhh1);

    dim3 g4(2, SS);
    out_gemm<<<g4, 256>>>(enc, Wpi, bpi, Wsg, bsg, Wmu, bmu, out);

    tail_kernel<<<1024 + BB, 256>>>(tgt, dur, out);
}